// round 1
// baseline (speedup 1.0000x reference)
#include <cuda_runtime.h>

// ---------------- problem constants ----------------
#define B_ 16
#define C_ 256
#define N_ 4096
#define M_ 1024
#define EPS_ 1e-5f

// ---------------- scratch (device globals; no allocation allowed) ----------------
__device__ float g_xm[B_ * C_];
__device__ float g_score[B_ * N_];
__device__ int   g_idx[2 * B_ * M_];
__device__ float g_ctx[2LL * B_ * M_ * C_];
__device__ float g_Q[(long long)B_ * N_ * C_];
__device__ float g_K[(long long)B_ * M_ * C_];
__device__ float g_V[(long long)B_ * M_ * C_];
__device__ float g_S[(long long)B_ * N_ * M_];
__device__ float g_Y[(long long)B_ * N_ * C_];
__device__ float g_Z[(long long)B_ * N_ * 2 * C_];  // concatenated [B,N,2C]: sharp cols 0..C-1, gentle C..2C-1
__device__ double g_sum[C_];
__device__ double g_sumsq[C_];
__device__ float g_bnw[C_];
__device__ float g_bnb[C_];

// ---------------- small kernels ----------------

__global__ void mean_kernel(const float* __restrict__ x) {
    int c = blockIdx.x, b = blockIdx.y, t = threadIdx.x;
    const float* p = x + ((long long)b * C_ + c) * N_;
    float s = 0.f;
    for (int i = t; i < N_; i += 256) s += p[i];
    __shared__ float sh[256];
    sh[t] = s; __syncthreads();
    for (int w = 128; w > 0; w >>= 1) { if (t < w) sh[t] += sh[t + w]; __syncthreads(); }
    if (t == 0) g_xm[b * C_ + c] = sh[0] * (1.0f / N_);
}

__global__ void score_kernel(const float* __restrict__ x) {
    int n = blockIdx.x * 256 + threadIdx.x;
    int b = blockIdx.y;
    const float* px = x + (long long)b * C_ * N_;
    const float* pm = g_xm + b * C_;
    float s = 0.f;
#pragma unroll 8
    for (int c = 0; c < C_; c++) {
        float d = px[(long long)c * N_ + n] - pm[c];
        s += d * d;
    }
    g_score[b * N_ + n] = s;  // squared norm: same ordering as norm
}

// per-batch bitonic sort descending of (score, index); top M -> sharp, bottom M -> gentle
__global__ void sort_kernel() {
    __shared__ float sv[N_];
    __shared__ int   si[N_];
    int b = blockIdx.x, t = threadIdx.x;  // 1024 threads
    for (int i = t; i < N_; i += 1024) { sv[i] = g_score[b * N_ + i]; si[i] = i; }
    __syncthreads();
    for (int k = 2; k <= N_; k <<= 1) {
        for (int j = k >> 1; j > 0; j >>= 1) {
            for (int i = t; i < N_; i += 1024) {
                int ixj = i ^ j;
                if (ixj > i) {
                    bool desc = ((i & k) == 0);
                    float a = sv[i], c = sv[ixj];
                    bool sw = desc ? (a < c) : (a > c);
                    if (sw) {
                        sv[i] = c; sv[ixj] = a;
                        int ta = si[i]; si[i] = si[ixj]; si[ixj] = ta;
                    }
                }
            }
            __syncthreads();
        }
    }
    for (int m = t; m < M_; m += 1024) {
        g_idx[0 * B_ * M_ + b * M_ + m] = si[m];            // sharp: largest M
        g_idx[1 * B_ * M_ + b * M_ + m] = si[N_ - M_ + m];  // gentle: smallest M
    }
}

__global__ void gather_kernel(const float* __restrict__ x) {
    int m = blockIdx.x, b = blockIdx.y, side = blockIdx.z;
    int j = g_idx[side * B_ * M_ + b * M_ + m];
    int c = threadIdx.x;  // 256
    g_ctx[(((long long)side * B_ + b) * M_ + m) * C_ + c] =
        x[((long long)b * C_ + c) * N_ + j];
}

__global__ void softmax_kernel() {
    int t = threadIdx.x;  // 256
    long long row = ((long long)blockIdx.y * N_ + blockIdx.x) * M_;
    float4* p = (float4*)(g_S + row);
    float4 v = p[t];
    __shared__ float sh[256];
    float mx = fmaxf(fmaxf(v.x, v.y), fmaxf(v.z, v.w));
    sh[t] = mx; __syncthreads();
    for (int w = 128; w > 0; w >>= 1) { if (t < w) sh[t] = fmaxf(sh[t], sh[t + w]); __syncthreads(); }
    float m = sh[0]; __syncthreads();
    v.x = expf(v.x - m); v.y = expf(v.y - m); v.z = expf(v.z - m); v.w = expf(v.w - m);
    float s = v.x + v.y + v.z + v.w;
    sh[t] = s; __syncthreads();
    for (int w = 128; w > 0; w >>= 1) { if (t < w) sh[t] += sh[t + w]; __syncthreads(); }
    float inv = 1.0f / sh[0];
    v.x *= inv; v.y *= inv; v.z *= inv; v.w *= inv;
    p[t] = v;
}

__global__ void bn_zero() {
    int t = threadIdx.x;
    if (t < C_) { g_sum[t] = 0.0; g_sumsq[t] = 0.0; }
}

__global__ void bn_stats(const float* __restrict__ pre) {
    int d = blockIdx.x, b = blockIdx.y, t = threadIdx.x;
    const float* p = pre + ((long long)b * C_ + d) * N_;
    float s = 0.f, s2 = 0.f;
    for (int i = t; i < N_; i += 256) { float v = p[i]; s += v; s2 += v * v; }
    __shared__ float sh[256];
    sh[t] = s; __syncthreads();
    for (int w = 128; w > 0; w >>= 1) { if (t < w) sh[t] += sh[t + w]; __syncthreads(); }
    float ts = sh[0]; __syncthreads();
    sh[t] = s2; __syncthreads();
    for (int w = 128; w > 0; w >>= 1) { if (t < w) sh[t] += sh[t + w]; __syncthreads(); }
    float ts2 = sh[0];
    if (t == 0) {
        atomicAdd(&g_sum[d], (double)ts);
        atomicAdd(&g_sumsq[d], (double)ts2);
    }
}

__global__ void bn_finalize(const float* __restrict__ gamma, const float* __restrict__ beta) {
    int d = threadIdx.x;  // 256
    double cnt = (double)B_ * N_;
    double mu = g_sum[d] / cnt;
    double var = g_sumsq[d] / cnt - mu * mu;
    float w = gamma[d] * rsqrtf((float)var + EPS_);
    g_bnw[d] = w;
    g_bnb[d] = beta[d] - (float)mu * w;
}

__global__ void bn_final(float* __restrict__ out) {
    int n = blockIdx.x * 256 + threadIdx.x;
    int d = blockIdx.y, b = blockIdx.z;
    long long o = ((long long)b * C_ + d) * N_ + n;
    float v = out[o] * g_bnw[d] + g_bnb[d];
    out[o] = v > 0.f ? v : 0.f;
}

// ---------------- generic tiled SGEMM ----------------
// C[i,j] = scale * sum_k A(i,k)*B(k,j) [+ bias] [+ R[j*ldr+i]]
// A(i,k) = TA ? A[k*lda+i] : A[i*lda+k]
// B(k,j) = TB ? B[j*ldb+k] : B[k*ldb+j]
// BIAS: 0 none, 1 per-column (bias[j]), 2 per-row (bias[i])
// All of Md, Nd are multiples of 128; Kd multiple of 16. No bounds checks.
template <bool TA, bool TB, int BIAS>
__global__ __launch_bounds__(256)
void gemm_kernel(const float* __restrict__ A, long long sA, int lda,
                 const float* __restrict__ Bm, long long sB, int ldb,
                 float* __restrict__ Cm, long long sC, int ldc,
                 int Kd,
                 const float* __restrict__ bias,
                 const float* __restrict__ R, long long sR, int ldr,
                 float scale) {
    const int bz = blockIdx.z;
    A  += (long long)bz * sA;
    Bm += (long long)bz * sB;
    Cm += (long long)bz * sC;
    if (R) R += (long long)bz * sR;
    const int row0 = blockIdx.y * 128;
    const int col0 = blockIdx.x * 128;

    __shared__ float As[16][128];
    __shared__ float Bs[16][128];

    const int tid = threadIdx.x;
    const int tx = tid & 15;
    const int ty = tid >> 4;

    float acc[8][8];
#pragma unroll
    for (int i = 0; i < 8; i++)
#pragma unroll
        for (int j = 0; j < 8; j++) acc[i][j] = 0.f;

    for (int k0 = 0; k0 < Kd; k0 += 16) {
        if (TA) {
            // A[k*lda + i]: load float4 along i (coalesced)
#pragma unroll
            for (int r = 0; r < 2; r++) {
                int lin = tid + r * 256;     // float4 id, 512 total
                int kk = lin >> 5;           // 0..15
                int i4 = (lin & 31) << 2;    // 0..124
                float4 v = *(const float4*)&A[(long long)(k0 + kk) * lda + row0 + i4];
                *(float4*)&As[kk][i4] = v;
            }
        } else {
            // A[i*lda + k]: load float4 along k, transpose into smem
#pragma unroll
            for (int r = 0; r < 2; r++) {
                int lin = tid + r * 256;
                int i  = lin >> 2;           // 0..127
                int k4 = (lin & 3) << 2;     // 0,4,8,12
                float4 v = *(const float4*)&A[(long long)(row0 + i) * lda + k0 + k4];
                As[k4 + 0][i] = v.x; As[k4 + 1][i] = v.y;
                As[k4 + 2][i] = v.z; As[k4 + 3][i] = v.w;
            }
        }
        if (TB) {
#pragma unroll
            for (int r = 0; r < 2; r++) {
                int lin = tid + r * 256;
                int j  = lin >> 2;
                int k4 = (lin & 3) << 2;
                float4 v = *(const float4*)&Bm[(long long)(col0 + j) * ldb + k0 + k4];
                Bs[k4 + 0][j] = v.x; Bs[k4 + 1][j] = v.y;
                Bs[k4 + 2][j] = v.z; Bs[k4 + 3][j] = v.w;
            }
        } else {
#pragma unroll
            for (int r = 0; r < 2; r++) {
                int lin = tid + r * 256;
                int kk = lin >> 5;
                int j4 = (lin & 31) << 2;
                float4 v = *(const float4*)&Bm[(long long)(k0 + kk) * ldb + col0 + j4];
                *(float4*)&Bs[kk][j4] = v;
            }
        }
        __syncthreads();
#pragma unroll
        for (int k = 0; k < 16; k++) {
            float a[8], b[8];
#pragma unroll
            for (int u = 0; u < 4; u++) {
                a[u]     = As[k][ty * 4 + u];
                a[4 + u] = As[k][64 + ty * 4 + u];
                b[u]     = Bs[k][tx * 4 + u];
                b[4 + u] = Bs[k][64 + tx * 4 + u];
            }
#pragma unroll
            for (int i = 0; i < 8; i++)
#pragma unroll
                for (int j = 0; j < 8; j++) acc[i][j] += a[i] * b[j];
        }
        __syncthreads();
    }

    // epilogue (vectorized stores)
    const int rb[2] = { row0 + ty * 4, row0 + 64 + ty * 4 };
    const int cb[2] = { col0 + tx * 4, col0 + 64 + tx * 4 };
#pragma unroll
    for (int ih = 0; ih < 2; ih++) {
#pragma unroll
        for (int u = 0; u < 4; u++) {
            int gi = rb[ih] + u;
#pragma unroll
            for (int jh = 0; jh < 2; jh++) {
                float4 v;
                float* vp = &v.x;
#pragma unroll
                for (int w = 0; w < 4; w++) {
                    int gj = cb[jh] + w;
                    float t = acc[ih * 4 + u][jh * 4 + w] * scale;
                    if (BIAS == 1) t += bias[gj];
                    if (BIAS == 2) t += bias[gi];
                    if (R) t += R[(long long)gj * ldr + gi];
                    vp[w] = t;
                }
                *(float4*)&Cm[(long long)gi * ldc + cb[jh]] = v;
            }
        }
    }
}

template <bool TA, bool TB, int BIAS>
static void launch_gemm(const float* A, long long sA, int lda,
                        const float* Bm, long long sB, int ldb,
                        float* Cm, long long sC, int ldc,
                        int Md, int Nd, int Kd,
                        const float* bias,
                        const float* R, long long sR, int ldr,
                        float scale, int batch) {
    dim3 grid(Nd / 128, Md / 128, batch);
    gemm_kernel<TA, TB, BIAS><<<grid, 256>>>(A, sA, lda, Bm, sB, ldb, Cm, sC, ldc,
                                             Kd, bias, R, sR, ldr, scale);
}

// ---------------- driver ----------------

extern "C" void kernel_launch(void* const* d_in, const int* in_sizes, int n_in,
                              void* d_out, int out_size) {
    const float* x = (const float*)d_in[0];
    // Robust to num_select placement: dict order has it at index 1 (size 1);
    // signature order has it last.
    int pb = (n_in > 1 && in_sizes[1] == 1) ? 2 : 1;
    const float* P[20];
    for (int i = 0; i < 20; i++) P[i] = (const float*)d_in[pb + i];
    // P[0..7]  = Wq_s,bq_s,Wk_s,bk_s,Wv_s,bv_s,Wo_s,bo_s
    // P[8..15] = gentle equivalents
    // P[16]=Wf, P[17]=bf, P[18]=gamma, P[19]=beta
    float* out = (float*)d_out;

    float *ctx, *Q, *K, *V, *S, *Y, *Z;
    cudaGetSymbolAddress((void**)&ctx, g_ctx);
    cudaGetSymbolAddress((void**)&Q, g_Q);
    cudaGetSymbolAddress((void**)&K, g_K);
    cudaGetSymbolAddress((void**)&V, g_V);
    cudaGetSymbolAddress((void**)&S, g_S);
    cudaGetSymbolAddress((void**)&Y, g_Y);
    cudaGetSymbolAddress((void**)&Z, g_Z);

    // 1) selection
    mean_kernel<<<dim3(C_, B_), 256>>>(x);
    score_kernel<<<dim3(N_ / 256, B_), 256>>>(x);
    sort_kernel<<<B_, 1024>>>();
    gather_kernel<<<dim3(M_, B_, 2), 256>>>(x);

    // 2) attention per side (sequential buffer reuse)
    for (int s = 0; s < 2; s++) {
        const float* Wq = P[8 * s + 0]; const float* bq = P[8 * s + 1];
        const float* Wk = P[8 * s + 2]; const float* bk = P[8 * s + 3];
        const float* Wv = P[8 * s + 4]; const float* bv = P[8 * s + 5];
        const float* Wo = P[8 * s + 6]; const float* bo = P[8 * s + 7];
        const float* ctxp = ctx + (long long)s * B_ * M_ * C_;

        // Q[b,n,d] = sum_c x[b,c,n] * Wq[d,c] + bq[d]
        launch_gemm<true, true, 1>(x, (long long)C_ * N_, N_,
                                   Wq, 0, C_,
                                   Q, (long long)N_ * C_, C_,
                                   N_, C_, C_, bq, nullptr, 0, 0, 1.f, B_);
        // K[b,m,d] = sum_c ctx[b,m,c] * Wk[d,c] + bk[d]
        launch_gemm<false, true, 1>(ctxp, (long long)M_ * C_, C_,
                                    Wk, 0, C_,
                                    K, (long long)M_ * C_, C_,
                                    M_, C_, C_, bk, nullptr, 0, 0, 1.f, B_);
        launch_gemm<false, true, 1>(ctxp, (long long)M_ * C_, C_,
                                    Wv, 0, C_,
                                    V, (long long)M_ * C_, C_,
                                    M_, C_, C_, bv, nullptr, 0, 0, 1.f, B_);
        // S[b,n,m] = (1/16) * sum_d Q[b,n,d] K[b,m,d]
        launch_gemm<false, true, 0>(Q, (long long)N_ * C_, C_,
                                    K, (long long)M_ * C_, C_,
                                    S, (long long)N_ * M_, M_,
                                    N_, M_, C_, nullptr, nullptr, 0, 0, 1.f / 16.f, B_);
        softmax_kernel<<<dim3(N_, B_), 256>>>();
        // Y[b,n,d] = sum_m P[b,n,m] V[b,m,d]
        launch_gemm<false, false, 0>(S, (long long)N_ * M_, M_,
                                     V, (long long)M_ * C_, C_,
                                     Y, (long long)N_ * C_, C_,
                                     N_, C_, M_, nullptr, nullptr, 0, 0, 1.f, B_);
        // Z[b,n,e] = x[b,e,n] + sum_d Y[b,n,d] Wo[e,d] + bo[e]   (into concat buffer)
        launch_gemm<false, true, 1>(Y, (long long)N_ * C_, C_,
                                    Wo, 0, C_,
                                    Z + s * C_, (long long)N_ * 2 * C_, 2 * C_,
                                    N_, C_, C_, bo,
                                    x, (long long)C_ * N_, N_, 1.f, B_);
    }

    // 3) fuse conv: out_pre[b,d,n] = sum_e Wf[d,e] * Zcat[b,n,e] + bf[d]
    launch_gemm<false, true, 2>(P[16], 0, 2 * C_,
                                Z, (long long)N_ * 2 * C_, 2 * C_,
                                out, (long long)C_ * N_, N_,
                                C_, N_, 2 * C_, P[17], nullptr, 0, 0, 1.f, B_);

    // 4) batchnorm (training stats) + ReLU in place
    bn_zero<<<1, 256>>>();
    bn_stats<<<dim3(C_, B_), 256>>>(out);
    bn_finalize<<<1, 256>>>(P[18], P[19]);
    bn_final<<<dim3(N_ / 256, C_, B_), 256>>>(out);
}

// round 2
// speedup vs baseline: 3.2495x; 3.2495x over previous
#include <cuda_runtime.h>
#include <cstdint>

// ---------------- problem constants ----------------
#define B_ 16
#define C_ 256
#define N_ 4096
#define M_ 1024
#define EPS_ 1e-5f

typedef long long ll;

// ---------------- scratch (device globals) ----------------
__device__ float g_xT[(ll)B_ * N_ * C_];          // exact x^T [b][n][c]
__device__ float g_xm[B_ * C_];
__device__ float g_score[B_ * N_];
__device__ int   g_idx[2 * B_ * M_];
__device__ float g_ctx[2LL * B_ * M_ * C_];       // tf32-rounded
__device__ float g_Q[(ll)B_ * N_ * C_];           // tf32-rounded
__device__ float g_K[(ll)B_ * M_ * C_];           // tf32-rounded
__device__ float g_Vt[(ll)B_ * C_ * M_];          // tf32-rounded, [b][d][m]
__device__ float g_S[(ll)B_ * N_ * M_];           // fp32 scores -> tf32 probs after softmax
__device__ float g_Y[(ll)B_ * N_ * C_];           // tf32-rounded
__device__ float g_Z[(ll)B_ * N_ * 2 * C_];       // tf32-rounded concat [b][n][2C]
__device__ float g_Wr[8 * C_ * C_ + C_ * 2 * C_]; // tf32-rounded weights
__device__ double g_sum[C_];
__device__ double g_sumsq[C_];
__device__ float g_bnw[C_];
__device__ float g_bnb[C_];

// ---------------- helpers ----------------
__device__ __forceinline__ float rna_tf32(float x) {
    float r; asm("cvt.rna.tf32.f32 %0, %1;" : "=f"(r) : "f"(x)); return r;
}

// ---------------- small kernels ----------------

__global__ void transpose_kernel(const float* __restrict__ x) {
    __shared__ float t[32][33];
    int b = blockIdx.z;
    int n0 = blockIdx.x * 32, c0 = blockIdx.y * 32;
    int tx = threadIdx.x, ty = threadIdx.y;  // (32, 8)
    const float* xp = x + (ll)b * C_ * N_;
    float* xtp = g_xT + (ll)b * N_ * C_;
#pragma unroll
    for (int i = 0; i < 32; i += 8)
        t[ty + i][tx] = xp[(ll)(c0 + ty + i) * N_ + n0 + tx];
    __syncthreads();
#pragma unroll
    for (int i = 0; i < 32; i += 8)
        xtp[(ll)(n0 + ty + i) * C_ + c0 + tx] = t[tx][ty + i];
}

__global__ void mean_kernel(const float* __restrict__ x) {
    int c = blockIdx.x, b = blockIdx.y, t = threadIdx.x;
    const float* p = x + ((ll)b * C_ + c) * N_;
    float s = 0.f;
    for (int i = t; i < N_; i += 256) s += p[i];
    __shared__ float sh[256];
    sh[t] = s; __syncthreads();
    for (int w = 128; w > 0; w >>= 1) { if (t < w) sh[t] += sh[t + w]; __syncthreads(); }
    if (t == 0) g_xm[b * C_ + c] = sh[0] * (1.0f / N_);
}

__global__ void score_kernel2() {
    int b = blockIdx.y;
    int w = threadIdx.x >> 5, lane = threadIdx.x & 31;
    int n = blockIdx.x * 8 + w;
    const float4* row = (const float4*)(g_xT + ((ll)b * N_ + n) * C_);
    const float4* mrow = (const float4*)(g_xm + b * C_);
    float s = 0.f;
#pragma unroll
    for (int j = lane; j < 64; j += 32) {
        float4 v = row[j], m = mrow[j];
        float dx = v.x - m.x, dy = v.y - m.y, dz = v.z - m.z, dw = v.w - m.w;
        s += dx * dx + dy * dy + dz * dz + dw * dw;
    }
#pragma unroll
    for (int o = 16; o; o >>= 1) s += __shfl_xor_sync(0xffffffffu, s, o);
    if (lane == 0) g_score[b * N_ + n] = s;
}

// per-batch bitonic sort descending; top M -> sharp, bottom M -> gentle
__global__ void sort_kernel() {
    __shared__ float sv[N_];
    __shared__ int   si[N_];
    int b = blockIdx.x, t = threadIdx.x;  // 1024 threads
    for (int i = t; i < N_; i += 1024) { sv[i] = g_score[b * N_ + i]; si[i] = i; }
    __syncthreads();
    for (int k = 2; k <= N_; k <<= 1) {
        for (int j = k >> 1; j > 0; j >>= 1) {
            for (int i = t; i < N_; i += 1024) {
                int ixj = i ^ j;
                if (ixj > i) {
                    bool desc = ((i & k) == 0);
                    float a = sv[i], c = sv[ixj];
                    bool sw = desc ? (a < c) : (a > c);
                    if (sw) {
                        sv[i] = c; sv[ixj] = a;
                        int ta = si[i]; si[i] = si[ixj]; si[ixj] = ta;
                    }
                }
            }
            __syncthreads();
        }
    }
    for (int m = t; m < M_; m += 1024) {
        g_idx[0 * B_ * M_ + b * M_ + m] = si[m];
        g_idx[1 * B_ * M_ + b * M_ + m] = si[N_ - M_ + m];
    }
}

__global__ void gather_kernel2() {
    int side = blockIdx.z, b = blockIdx.y;
    int m = blockIdx.x * 4 + (threadIdx.x >> 6);
    int c4 = threadIdx.x & 63;
    int j = g_idx[side * B_ * M_ + b * M_ + m];
    const float4* src = (const float4*)(g_xT + ((ll)b * N_ + j) * C_);
    float4 v = src[c4];
    v.x = rna_tf32(v.x); v.y = rna_tf32(v.y); v.z = rna_tf32(v.z); v.w = rna_tf32(v.w);
    ((float4*)(g_ctx + (((ll)side * B_ + b) * M_ + m) * C_))[c4] = v;
}

__global__ void round_copy(const float* __restrict__ src, float* __restrict__ dst, int n) {
    int i = blockIdx.x * 256 + threadIdx.x;
    if (i < n) dst[i] = rna_tf32(src[i]);
}

__global__ void softmax_kernel() {
    int t = threadIdx.x;  // 256
    ll row = ((ll)blockIdx.y * N_ + blockIdx.x) * M_;
    float4* p = (float4*)(g_S + row);
    float4 v = p[t];
    __shared__ float sh[256];
    float mx = fmaxf(fmaxf(v.x, v.y), fmaxf(v.z, v.w));
    sh[t] = mx; __syncthreads();
    for (int w = 128; w > 0; w >>= 1) { if (t < w) sh[t] = fmaxf(sh[t], sh[t + w]); __syncthreads(); }
    float m = sh[0]; __syncthreads();
    v.x = expf(v.x - m); v.y = expf(v.y - m); v.z = expf(v.z - m); v.w = expf(v.w - m);
    float s = v.x + v.y + v.z + v.w;
    sh[t] = s; __syncthreads();
    for (int w = 128; w > 0; w >>= 1) { if (t < w) sh[t] += sh[t + w]; __syncthreads(); }
    float inv = 1.0f / sh[0];
    v.x = rna_tf32(v.x * inv); v.y = rna_tf32(v.y * inv);
    v.z = rna_tf32(v.z * inv); v.w = rna_tf32(v.w * inv);
    p[t] = v;
}

__global__ void bn_zero() {
    int t = threadIdx.x;
    if (t < C_) { g_sum[t] = 0.0; g_sumsq[t] = 0.0; }
}

__global__ void bn_stats(const float* __restrict__ pre) {
    int d = blockIdx.x, b = blockIdx.y, t = threadIdx.x;
    const float* p = pre + ((ll)b * C_ + d) * N_;
    float s = 0.f, s2 = 0.f;
    for (int i = t; i < N_; i += 256) { float v = p[i]; s += v; s2 += v * v; }
    __shared__ float sh[256];
    sh[t] = s; __syncthreads();
    for (int w = 128; w > 0; w >>= 1) { if (t < w) sh[t] += sh[t + w]; __syncthreads(); }
    float ts = sh[0]; __syncthreads();
    sh[t] = s2; __syncthreads();
    for (int w = 128; w > 0; w >>= 1) { if (t < w) sh[t] += sh[t + w]; __syncthreads(); }
    float ts2 = sh[0];
    if (t == 0) {
        atomicAdd(&g_sum[d], (double)ts);
        atomicAdd(&g_sumsq[d], (double)ts2);
    }
}

__global__ void bn_finalize(const float* __restrict__ gamma, const float* __restrict__ beta) {
    int d = threadIdx.x;  // 256
    double cnt = (double)B_ * N_;
    double mu = g_sum[d] / cnt;
    double var = g_sumsq[d] / cnt - mu * mu;
    float w = gamma[d] * rsqrtf((float)var + EPS_);
    g_bnw[d] = w;
    g_bnb[d] = beta[d] - (float)mu * w;
}

__global__ void bn_final(float* __restrict__ out) {
    int n = blockIdx.x * 256 + threadIdx.x;
    int d = blockIdx.y, b = blockIdx.z;
    ll o = ((ll)b * C_ + d) * N_ + n;
    float v = out[o] * g_bnw[d] + g_bnb[d];
    out[o] = v > 0.f ? v : 0.f;
}

// ---------------- tf32 tensor-core TN GEMM ----------------
// C[i,j] = scale * sum_k A[i*lda+k] * B[j*ldb+k]  (+bias)(+R[i*ldr+j])(-> tf32 round)
// Tiles: 128x128x32, 256 threads, warp tile 64x32, m16n8k8 tf32 mma.

#define TMm 128
#define TNn 128
#define TKk 32
#define SMEM_STAGE (2 * TMm * TKk)        // floats: A tile + B tile
#define GSMEM_BYTES (2 * SMEM_STAGE * 4)  // 2 stages

__device__ __forceinline__ void cp16(uint32_t dst, const float* src) {
    asm volatile("cp.async.cg.shared.global [%0], [%1], 16;" :: "r"(dst), "l"(src));
}
__device__ __forceinline__ void cp_commit() { asm volatile("cp.async.commit_group;"); }
template <int Nw> __device__ __forceinline__ void cp_wait() {
    asm volatile("cp.async.wait_group %0;" :: "n"(Nw));
}
__device__ __forceinline__ void ldsm_x4(uint32_t* r, uint32_t addr) {
    asm volatile("ldmatrix.sync.aligned.m8n8.x4.shared.b16 {%0,%1,%2,%3}, [%4];"
        : "=r"(r[0]), "=r"(r[1]), "=r"(r[2]), "=r"(r[3]) : "r"(addr));
}
__device__ __forceinline__ void ldsm_x2(uint32_t* r, uint32_t addr) {
    asm volatile("ldmatrix.sync.aligned.m8n8.x2.shared.b16 {%0,%1}, [%2];"
        : "=r"(r[0]), "=r"(r[1]) : "r"(addr));
}
__device__ __forceinline__ void mma_tf32(float* c, const uint32_t* a, const uint32_t* b) {
    asm volatile("mma.sync.aligned.m16n8k8.row.col.f32.tf32.tf32.f32 "
        "{%0,%1,%2,%3}, {%4,%5,%6,%7}, {%8,%9}, {%0,%1,%2,%3};"
        : "+f"(c[0]), "+f"(c[1]), "+f"(c[2]), "+f"(c[3])
        : "r"(a[0]), "r"(a[1]), "r"(a[2]), "r"(a[3]), "r"(b[0]), "r"(b[1]));
}

// BIAS: 0 none, 1 per-col (bias[j]), 2 per-row (bias[i])
template <int BIAS, bool RES, bool ROUND>
__global__ __launch_bounds__(256, 2)
void gemm_tn(const float* __restrict__ A, ll sA, int lda,
             const float* __restrict__ Bg, ll sB, int ldb,
             float* __restrict__ Cm, ll sC, int ldc,
             int Kd,
             const float* __restrict__ bias,
             const float* __restrict__ R, ll sR, int ldr,
             float scale) {
    extern __shared__ float sm[];
    const int bz = blockIdx.z;
    A += (ll)bz * sA; Bg += (ll)bz * sB; Cm += (ll)bz * sC;
    if (RES) R += (ll)bz * sR;
    const int row0 = blockIdx.y * TMm;
    const int col0 = blockIdx.x * TNn;
    const int tid = threadIdx.x;
    const uint32_t smu = (uint32_t)__cvta_generic_to_shared(sm);

    const int lane = tid & 31, warp = tid >> 5;
    const int wm = warp >> 2, wn = warp & 3;
    const int midA = lane >> 3;
    const int rowA0 = wm * 64 + (lane & 7) + ((midA & 1) << 3);  // + mt*16
    const int f4selA = midA >> 1;
    const int rxa = rowA0 & 7;
    const int tb = lane & 15;
    const int rowB0 = wn * 32 + (tb & 7);  // + nt*8
    const int midB = tb >> 3;
    const int rxb = tb & 7;

    float acc[4][4][4];
#pragma unroll
    for (int i = 0; i < 4; i++)
#pragma unroll
        for (int j = 0; j < 4; j++)
#pragma unroll
            for (int q = 0; q < 4; q++) acc[i][j][q] = 0.f;

    const int nT = Kd / TKk;

    // prologue: stage tile 0
    {
#pragma unroll
        for (int r = 0; r < 4; r++) {
            int lin = tid + r * 256;
            int row = lin >> 3, f4 = lin & 7;
            uint32_t soff = (uint32_t)(row * 32 + ((f4 ^ (row & 7)) << 2));
            cp16(smu + soff * 4, A + (size_t)(row0 + row) * lda + f4 * 4);
            cp16(smu + (TMm * TKk + soff) * 4, Bg + (size_t)(col0 + row) * ldb + f4 * 4);
        }
        cp_commit();
    }

    for (int t = 0; t < nT; t++) {
        if (t + 1 < nT) {
            const int st = (t + 1) & 1;
            const int k0 = (t + 1) * TKk;
#pragma unroll
            for (int r = 0; r < 4; r++) {
                int lin = tid + r * 256;
                int row = lin >> 3, f4 = lin & 7;
                uint32_t soff = (uint32_t)(st * SMEM_STAGE + row * 32 + ((f4 ^ (row & 7)) << 2));
                cp16(smu + soff * 4, A + (size_t)(row0 + row) * lda + k0 + f4 * 4);
                cp16(smu + (TMm * TKk + soff) * 4, Bg + (size_t)(col0 + row) * ldb + k0 + f4 * 4);
            }
            cp_commit();
            cp_wait<1>();
        } else {
            cp_wait<0>();
        }
        __syncthreads();

        const uint32_t Au = smu + (uint32_t)((t & 1) * SMEM_STAGE) * 4;
        const uint32_t Bu = Au + TMm * TKk * 4;
#pragma unroll
        for (int kt = 0; kt < 4; kt++) {
            uint32_t af[4][4], bf[4][2];
#pragma unroll
            for (int mt = 0; mt < 4; mt++) {
                int row = rowA0 + mt * 16;
                uint32_t off = (uint32_t)(row * 32 + (((kt * 2 + f4selA) ^ rxa) << 2));
                ldsm_x4(af[mt], Au + off * 4);
            }
#pragma unroll
            for (int nt = 0; nt < 4; nt++) {
                int row = rowB0 + nt * 8;
                uint32_t off = (uint32_t)(row * 32 + (((kt * 2 + midB) ^ rxb) << 2));
                ldsm_x2(bf[nt], Bu + off * 4);
            }
#pragma unroll
            for (int mt = 0; mt < 4; mt++)
#pragma unroll
                for (int nt = 0; nt < 4; nt++)
                    mma_tf32(acc[mt][nt], af[mt], bf[nt]);
        }
        __syncthreads();
    }

    // epilogue
    const int gr = lane >> 2, gc = (lane & 3) * 2;
#pragma unroll
    for (int mt = 0; mt < 4; mt++) {
        int r0 = row0 + wm * 64 + mt * 16 + gr;
#pragma unroll
        for (int nt = 0; nt < 4; nt++) {
            int col = col0 + wn * 32 + nt * 8 + gc;
            float v0x = acc[mt][nt][0] * scale, v0y = acc[mt][nt][1] * scale;
            float v1x = acc[mt][nt][2] * scale, v1y = acc[mt][nt][3] * scale;
            if (BIAS == 1) {
                float bx = bias[col], by = bias[col + 1];
                v0x += bx; v0y += by; v1x += bx; v1y += by;
            } else if (BIAS == 2) {
                float b0v = bias[r0], b1v = bias[r0 + 8];
                v0x += b0v; v0y += b0v; v1x += b1v; v1y += b1v;
            }
            if (RES) {
                float2 ra = *(const float2*)&R[(size_t)r0 * ldr + col];
                float2 rb = *(const float2*)&R[(size_t)(r0 + 8) * ldr + col];
                v0x += ra.x; v0y += ra.y; v1x += rb.x; v1y += rb.y;
            }
            if (ROUND) {
                v0x = rna_tf32(v0x); v0y = rna_tf32(v0y);
                v1x = rna_tf32(v1x); v1y = rna_tf32(v1y);
            }
            *(float2*)&Cm[(size_t)r0 * ldc + col] = make_float2(v0x, v0y);
            *(float2*)&Cm[(size_t)(r0 + 8) * ldc + col] = make_float2(v1x, v1y);
        }
    }
}

template <int BIAS, bool RES, bool ROUND>
static void launch_tn(const float* A, ll sA, int lda,
                      const float* Bg, ll sB, int ldb,
                      float* Cm, ll sC, int ldc,
                      int Md, int Nd, int Kd,
                      const float* bias,
                      const float* R, ll sR, int ldr,
                      float scale, int batch) {
    cudaFuncSetAttribute(gemm_tn<BIAS, RES, ROUND>,
                         cudaFuncAttributeMaxDynamicSharedMemorySize, GSMEM_BYTES);
    dim3 grid(Nd / TNn, Md / TMm, batch);
    gemm_tn<BIAS, RES, ROUND><<<grid, 256, GSMEM_BYTES>>>(
        A, sA, lda, Bg, sB, ldb, Cm, sC, ldc, Kd, bias, R, sR, ldr, scale);
}

// ---------------- driver ----------------

extern "C" void kernel_launch(void* const* d_in, const int* in_sizes, int n_in,
                              void* d_out, int out_size) {
    const float* x = (const float*)d_in[0];
    int pb = (n_in > 1 && in_sizes[1] == 1) ? 2 : 1;
    const float* P[20];
    for (int i = 0; i < 20; i++) P[i] = (const float*)d_in[pb + i];
    float* out = (float*)d_out;

    float *xT, *ctx, *Q, *K, *Vt, *S, *Y, *Z, *Wr;
    cudaGetSymbolAddress((void**)&xT, g_xT);
    cudaGetSymbolAddress((void**)&ctx, g_ctx);
    cudaGetSymbolAddress((void**)&Q, g_Q);
    cudaGetSymbolAddress((void**)&K, g_K);
    cudaGetSymbolAddress((void**)&Vt, g_Vt);
    cudaGetSymbolAddress((void**)&S, g_S);
    cudaGetSymbolAddress((void**)&Y, g_Y);
    cudaGetSymbolAddress((void**)&Z, g_Z);
    cudaGetSymbolAddress((void**)&Wr, g_Wr);

    const int CC = C_ * C_;

    // 1) transpose + selection
    transpose_kernel<<<dim3(N_ / 32, C_ / 32, B_), dim3(32, 8)>>>(x);
    mean_kernel<<<dim3(C_, B_), 256>>>(x);
    score_kernel2<<<dim3(N_ / 8, B_), 256>>>();
    sort_kernel<<<B_, 1024>>>();
    gather_kernel2<<<dim3(M_ / 4, B_, 2), 256>>>();

    // 2) round weights to tf32
    for (int s = 0; s < 2; s++)
        for (int w = 0; w < 4; w++)
            round_copy<<<CC / 256, 256>>>(P[8 * s + 2 * w], Wr + (s * 4 + w) * CC, CC);
    round_copy<<<(2 * CC) / 256, 256>>>(P[16], Wr + 8 * CC, 2 * CC);

    // 3) attention per side
    for (int s = 0; s < 2; s++) {
        const float* Wq = Wr + (s * 4 + 0) * CC; const float* bq = P[8 * s + 1];
        const float* Wk = Wr + (s * 4 + 1) * CC; const float* bk = P[8 * s + 3];
        const float* Wv = Wr + (s * 4 + 2) * CC; const float* bv = P[8 * s + 5];
        const float* Wo = Wr + (s * 4 + 3) * CC; const float* bo = P[8 * s + 7];
        const float* ctxp = ctx + (ll)s * B_ * M_ * C_;

        // Q[b,n,d] = xT[n,:]·Wq[d,:] + bq[d]
        launch_tn<1, false, true>(xT, (ll)N_ * C_, C_, Wq, 0, C_,
                                  Q, (ll)N_ * C_, C_, N_, C_, C_,
                                  bq, nullptr, 0, 0, 1.f, B_);
        // K[b,m,d] = ctx[m,:]·Wk[d,:] + bk[d]
        launch_tn<1, false, true>(ctxp, (ll)M_ * C_, C_, Wk, 0, C_,
                                  K, (ll)M_ * C_, C_, M_, C_, C_,
                                  bk, nullptr, 0, 0, 1.f, B_);
        // Vt[b,d,m] = Wv[d,:]·ctx[m,:] + bv[d]
        launch_tn<2, false, true>(Wv, 0, C_, ctxp, (ll)M_ * C_, C_,
                                  Vt, (ll)C_ * M_, M_, C_, M_, C_,
                                  bv, nullptr, 0, 0, 1.f, B_);
        // S[b,n,m] = Q[n,:]·K[m,:] / 16
        launch_tn<0, false, false>(Q, (ll)N_ * C_, C_, K, (ll)M_ * C_, C_,
                                   S, (ll)N_ * M_, M_, N_, M_, C_,
                                   nullptr, nullptr, 0, 0, 1.f / 16.f, B_);
        softmax_kernel<<<dim3(N_, B_), 256>>>();
        // Y[b,n,d] = P[n,:]·Vt[d,:]
        launch_tn<0, false, true>(S, (ll)N_ * M_, M_, Vt, (ll)C_ * M_, M_,
                                  Y, (ll)N_ * C_, C_, N_, C_, M_,
                                  nullptr, nullptr, 0, 0, 1.f, B_);
        // Z[b,n,e](concat slot s) = Y[n,:]·Wo[e,:] + bo[e] + xT[n,e]
        launch_tn<1, true, true>(Y, (ll)N_ * C_, C_, Wo, 0, C_,
                                 Z + s * C_, (ll)N_ * 2 * C_, 2 * C_,
                                 N_, C_, C_, bo, xT, (ll)N_ * C_, C_, 1.f, B_);
    }

    // 4) fuse conv: out[b,d,n] = Wf[d,:]·Zcat[n,:] + bf[d]
    launch_tn<2, false, false>(Wr + 8 * CC, 0, 2 * C_, Z, (ll)N_ * 2 * C_, 2 * C_,
                               out, (ll)C_ * N_, N_, C_, N_, 2 * C_,
                               P[17], nullptr, 0, 0, 1.f, B_);

    // 5) batchnorm + ReLU in place
    bn_zero<<<1, 256>>>();
    bn_stats<<<dim3(C_, B_), 256>>>(out);
    bn_finalize<<<1, 256>>>(P[18], P[19]);
    bn_final<<<dim3(N_ / 256, C_, B_), 256>>>(out);
}

// round 3
// speedup vs baseline: 3.2626x; 1.0040x over previous
#include <cuda_runtime.h>
#include <cstdint>

// ---------------- problem constants ----------------
#define B_ 16
#define C_ 256
#define N_ 4096
#define M_ 1024
#define EPS_ 1e-5f

typedef long long ll;

// ---------------- scratch (device globals) ----------------
__device__ float g_xT[(ll)B_ * N_ * C_];          // exact x^T [b][n][c]
__device__ float g_xm[B_ * C_];
__device__ float g_score[B_ * N_];
__device__ int   g_idx[2 * B_ * M_];
__device__ float g_ctx[2LL * B_ * M_ * C_];       // tf32-rounded
__device__ float g_Q[(ll)B_ * N_ * C_];           // tf32-rounded
__device__ float g_K[(ll)B_ * M_ * C_];           // tf32-rounded
__device__ float g_Vt[(ll)B_ * C_ * M_];          // tf32-rounded, [b][d][m]
__device__ float g_S[(ll)B_ * N_ * M_];           // fp32 scores -> tf32 probs after softmax
__device__ float g_Y[(ll)B_ * N_ * C_];           // tf32-rounded
__device__ float g_Z[(ll)B_ * N_ * 2 * C_];       // tf32-rounded concat [b][n][2C]
__device__ float g_Wr[8 * C_ * C_ + C_ * 2 * C_]; // tf32-rounded weights
__device__ double g_sum[C_];
__device__ double g_sumsq[C_];
__device__ float g_bnw[C_];
__device__ float g_bnb[C_];

// ---------------- helpers ----------------
__device__ __forceinline__ float rna_tf32(float x) {
    float r; asm("cvt.rna.tf32.f32 %0, %1;" : "=f"(r) : "f"(x)); return r;
}

// ---------------- small kernels ----------------

__global__ void transpose_kernel(const float* __restrict__ x) {
    __shared__ float t[32][33];
    int b = blockIdx.z;
    int n0 = blockIdx.x * 32, c0 = blockIdx.y * 32;
    int tx = threadIdx.x, ty = threadIdx.y;  // (32, 8)
    const float* xp = x + (ll)b * C_ * N_;
    float* xtp = g_xT + (ll)b * N_ * C_;
#pragma unroll
    for (int i = 0; i < 32; i += 8)
        t[ty + i][tx] = xp[(ll)(c0 + ty + i) * N_ + n0 + tx];
    __syncthreads();
#pragma unroll
    for (int i = 0; i < 32; i += 8)
        xtp[(ll)(n0 + ty + i) * C_ + c0 + tx] = t[tx][ty + i];
}

__global__ void mean_kernel(const float* __restrict__ x) {
    int c = blockIdx.x, b = blockIdx.y, t = threadIdx.x;
    const float* p = x + ((ll)b * C_ + c) * N_;
    float s = 0.f;
    for (int i = t; i < N_; i += 256) s += p[i];
    __shared__ float sh[256];
    sh[t] = s; __syncthreads();
    for (int w = 128; w > 0; w >>= 1) { if (t < w) sh[t] += sh[t + w]; __syncthreads(); }
    if (t == 0) g_xm[b * C_ + c] = sh[0] * (1.0f / N_);
}

__global__ void score_kernel2() {
    int b = blockIdx.y;
    int w = threadIdx.x >> 5, lane = threadIdx.x & 31;
    int n = blockIdx.x * 8 + w;
    const float4* row = (const float4*)(g_xT + ((ll)b * N_ + n) * C_);
    const float4* mrow = (const float4*)(g_xm + b * C_);
    float s = 0.f;
#pragma unroll
    for (int j = lane; j < 64; j += 32) {
        float4 v = row[j], m = mrow[j];
        float dx = v.x - m.x, dy = v.y - m.y, dz = v.z - m.z, dw = v.w - m.w;
        s += dx * dx + dy * dy + dz * dz + dw * dw;
    }
#pragma unroll
    for (int o = 16; o; o >>= 1) s += __shfl_xor_sync(0xffffffffu, s, o);
    if (lane == 0) g_score[b * N_ + n] = s;
}

// per-batch bitonic sort descending; top M -> sharp, bottom M -> gentle
__global__ void sort_kernel() {
    __shared__ float sv[N_];
    __shared__ int   si[N_];
    int b = blockIdx.x, t = threadIdx.x;  // 1024 threads
    for (int i = t; i < N_; i += 1024) { sv[i] = g_score[b * N_ + i]; si[i] = i; }
    __syncthreads();
    for (int k = 2; k <= N_; k <<= 1) {
        for (int j = k >> 1; j > 0; j >>= 1) {
            for (int i = t; i < N_; i += 1024) {
                int ixj = i ^ j;
                if (ixj > i) {
                    bool desc = ((i & k) == 0);
                    float a = sv[i], c = sv[ixj];
                    bool sw = desc ? (a < c) : (a > c);
                    if (sw) {
                        sv[i] = c; sv[ixj] = a;
                        int ta = si[i]; si[i] = si[ixj]; si[ixj] = ta;
                    }
                }
            }
            __syncthreads();
        }
    }
    for (int m = t; m < M_; m += 1024) {
        g_idx[0 * B_ * M_ + b * M_ + m] = si[m];
        g_idx[1 * B_ * M_ + b * M_ + m] = si[N_ - M_ + m];
    }
}

__global__ void gather_kernel2() {
    int side = blockIdx.z, b = blockIdx.y;
    int m = blockIdx.x * 4 + (threadIdx.x >> 6);
    int c4 = threadIdx.x & 63;
    int j = g_idx[side * B_ * M_ + b * M_ + m];
    const float4* src = (const float4*)(g_xT + ((ll)b * N_ + j) * C_);
    float4 v = src[c4];
    v.x = rna_tf32(v.x); v.y = rna_tf32(v.y); v.z = rna_tf32(v.z); v.w = rna_tf32(v.w);
    ((float4*)(g_ctx + (((ll)side * B_ + b) * M_ + m) * C_))[c4] = v;
}

__global__ void round_copy(const float* __restrict__ src, float* __restrict__ dst, int n) {
    int i = blockIdx.x * 256 + threadIdx.x;
    if (i < n) dst[i] = rna_tf32(src[i]);
}

__global__ void softmax_kernel() {
    int t = threadIdx.x;  // 256
    ll row = ((ll)blockIdx.y * N_ + blockIdx.x) * M_;
    float4* p = (float4*)(g_S + row);
    float4 v = p[t];
    __shared__ float sh[256];
    float mx = fmaxf(fmaxf(v.x, v.y), fmaxf(v.z, v.w));
    sh[t] = mx; __syncthreads();
    for (int w = 128; w > 0; w >>= 1) { if (t < w) sh[t] = fmaxf(sh[t], sh[t + w]); __syncthreads(); }
    float m = sh[0]; __syncthreads();
    v.x = expf(v.x - m); v.y = expf(v.y - m); v.z = expf(v.z - m); v.w = expf(v.w - m);
    float s = v.x + v.y + v.z + v.w;
    sh[t] = s; __syncthreads();
    for (int w = 128; w > 0; w >>= 1) { if (t < w) sh[t] += sh[t + w]; __syncthreads(); }
    float inv = 1.0f / sh[0];
    v.x = rna_tf32(v.x * inv); v.y = rna_tf32(v.y * inv);
    v.z = rna_tf32(v.z * inv); v.w = rna_tf32(v.w * inv);
    p[t] = v;
}

__global__ void bn_zero() {
    int t = threadIdx.x;
    if (t < C_) { g_sum[t] = 0.0; g_sumsq[t] = 0.0; }
}

__global__ void bn_stats(const float* __restrict__ pre) {
    int d = blockIdx.x, b = blockIdx.y, t = threadIdx.x;
    const float* p = pre + ((ll)b * C_ + d) * N_;
    float s = 0.f, s2 = 0.f;
    for (int i = t; i < N_; i += 256) { float v = p[i]; s += v; s2 += v * v; }
    __shared__ float sh[256];
    sh[t] = s; __syncthreads();
    for (int w = 128; w > 0; w >>= 1) { if (t < w) sh[t] += sh[t + w]; __syncthreads(); }
    float ts = sh[0]; __syncthreads();
    sh[t] = s2; __syncthreads();
    for (int w = 128; w > 0; w >>= 1) { if (t < w) sh[t] += sh[t + w]; __syncthreads(); }
    float ts2 = sh[0];
    if (t == 0) {
        atomicAdd(&g_sum[d], (double)ts);
        atomicAdd(&g_sumsq[d], (double)ts2);
    }
}

__global__ void bn_finalize(const float* __restrict__ gamma, const float* __restrict__ beta) {
    int d = threadIdx.x;  // 256
    double cnt = (double)B_ * N_;
    double mu = g_sum[d] / cnt;
    double var = g_sumsq[d] / cnt - mu * mu;
    float w = gamma[d] * rsqrtf((float)var + EPS_);
    g_bnw[d] = w;
    g_bnb[d] = beta[d] - (float)mu * w;
}

__global__ void bn_final(float* __restrict__ out) {
    int n = blockIdx.x * 256 + threadIdx.x;
    int d = blockIdx.y, b = blockIdx.z;
    ll o = ((ll)b * C_ + d) * N_ + n;
    float v = out[o] * g_bnw[d] + g_bnb[d];
    out[o] = v > 0.f ? v : 0.f;
}

// ---------------- tf32 tensor-core TN GEMM ----------------
// C[i,j] = scale * sum_k A[i*lda+k] * B[j*ldb+k]  (+bias)(+R[i*ldr+j])(-> tf32 round)
// Tiles: 128x128x32, 256 threads, warp tile 64x32, m16n8k8 tf32 mma.

#define TMm 128
#define TNn 128
#define TKk 32
#define SMEM_STAGE (2 * TMm * TKk)        // floats: A tile + B tile
#define GSMEM_BYTES (2 * SMEM_STAGE * 4)  // 2 stages

__device__ __forceinline__ void cp16(uint32_t dst, const float* src) {
    asm volatile("cp.async.cg.shared.global [%0], [%1], 16;" :: "r"(dst), "l"(src));
}
__device__ __forceinline__ void cp_commit() { asm volatile("cp.async.commit_group;"); }
template <int Nw> __device__ __forceinline__ void cp_wait() {
    asm volatile("cp.async.wait_group %0;" :: "n"(Nw));
}
__device__ __forceinline__ void ldsm_x4(uint32_t* r, uint32_t addr) {
    asm volatile("ldmatrix.sync.aligned.m8n8.x4.shared.b16 {%0,%1,%2,%3}, [%4];"
        : "=r"(r[0]), "=r"(r[1]), "=r"(r[2]), "=r"(r[3]) : "r"(addr));
}
__device__ __forceinline__ void ldsm_x2(uint32_t* r, uint32_t addr) {
    asm volatile("ldmatrix.sync.aligned.m8n8.x2.shared.b16 {%0,%1}, [%2];"
        : "=r"(r[0]), "=r"(r[1]) : "r"(addr));
}
__device__ __forceinline__ void mma_tf32(float* c, const uint32_t* a, const uint32_t* b) {
    asm volatile("mma.sync.aligned.m16n8k8.row.col.f32.tf32.tf32.f32 "
        "{%0,%1,%2,%3}, {%4,%5,%6,%7}, {%8,%9}, {%0,%1,%2,%3};"
        : "+f"(c[0]), "+f"(c[1]), "+f"(c[2]), "+f"(c[3])
        : "r"(a[0]), "r"(a[1]), "r"(a[2]), "r"(a[3]), "r"(b[0]), "r"(b[1]));
}

// BIAS: 0 none, 1 per-col (bias[j]), 2 per-row (bias[i])
template <int BIAS, bool RES, bool ROUND>
__global__ __launch_bounds__(256, 2)
void gemm_tn(const float* __restrict__ A, ll sA, int lda,
             const float* __restrict__ Bg, ll sB, int ldb,
             float* __restrict__ Cm, ll sC, int ldc,
             int Kd,
             const float* __restrict__ bias,
             const float* __restrict__ R, ll sR, int ldr,
             float scale) {
    extern __shared__ float sm[];
    const int bz = blockIdx.z;
    A += (ll)bz * sA; Bg += (ll)bz * sB; Cm += (ll)bz * sC;
    if (RES) R += (ll)bz * sR;
    const int row0 = blockIdx.y * TMm;
    const int col0 = blockIdx.x * TNn;
    const int tid = threadIdx.x;
    const uint32_t smu = (uint32_t)__cvta_generic_to_shared(sm);

    const int lane = tid & 31, warp = tid >> 5;
    const int wm = warp >> 2, wn = warp & 3;
    const int midA = lane >> 3;
    const int rowA0 = wm * 64 + (lane & 7) + ((midA & 1) << 3);  // + mt*16
    const int f4selA = midA >> 1;
    const int rxa = rowA0 & 7;
    const int tb = lane & 15;
    const int rowB0 = wn * 32 + (tb & 7);  // + nt*8
    const int midB = tb >> 3;
    const int rxb = tb & 7;

    float acc[4][4][4];
#pragma unroll
    for (int i = 0; i < 4; i++)
#pragma unroll
        for (int j = 0; j < 4; j++)
#pragma unroll
            for (int q = 0; q < 4; q++) acc[i][j][q] = 0.f;

    const int nT = Kd / TKk;

    // prologue: stage tile 0
    {
#pragma unroll
        for (int r = 0; r < 4; r++) {
            int lin = tid + r * 256;
            int row = lin >> 3, f4 = lin & 7;
            uint32_t soff = (uint32_t)(row * 32 + ((f4 ^ (row & 7)) << 2));
            cp16(smu + soff * 4, A + (size_t)(row0 + row) * lda + f4 * 4);
            cp16(smu + (TMm * TKk + soff) * 4, Bg + (size_t)(col0 + row) * ldb + f4 * 4);
        }
        cp_commit();
    }

    for (int t = 0; t < nT; t++) {
        if (t + 1 < nT) {
            const int st = (t + 1) & 1;
            const int k0 = (t + 1) * TKk;
#pragma unroll
            for (int r = 0; r < 4; r++) {
                int lin = tid + r * 256;
                int row = lin >> 3, f4 = lin & 7;
                uint32_t soff = (uint32_t)(st * SMEM_STAGE + row * 32 + ((f4 ^ (row & 7)) << 2));
                cp16(smu + soff * 4, A + (size_t)(row0 + row) * lda + k0 + f4 * 4);
                cp16(smu + (TMm * TKk + soff) * 4, Bg + (size_t)(col0 + row) * ldb + k0 + f4 * 4);
            }
            cp_commit();
            cp_wait<1>();
        } else {
            cp_wait<0>();
        }
        __syncthreads();

        const uint32_t Au = smu + (uint32_t)((t & 1) * SMEM_STAGE) * 4;
        const uint32_t Bu = Au + TMm * TKk * 4;
#pragma unroll
        for (int kt = 0; kt < 4; kt++) {
            uint32_t af[4][4], bf[4][2];
#pragma unroll
            for (int mt = 0; mt < 4; mt++) {
                int row = rowA0 + mt * 16;
                uint32_t off = (uint32_t)(row * 32 + (((kt * 2 + f4selA) ^ rxa) << 2));
                ldsm_x4(af[mt], Au + off * 4);
            }
#pragma unroll
            for (int nt = 0; nt < 4; nt++) {
                int row = rowB0 + nt * 8;
                uint32_t off = (uint32_t)(row * 32 + (((kt * 2 + midB) ^ rxb) << 2));
                ldsm_x2(bf[nt], Bu + off * 4);
            }
#pragma unroll
            for (int mt = 0; mt < 4; mt++)
#pragma unroll
                for (int nt = 0; nt < 4; nt++)
                    mma_tf32(acc[mt][nt], af[mt], bf[nt]);
        }
        __syncthreads();
    }

    // epilogue
    const int gr = lane >> 2, gc = (lane & 3) * 2;
#pragma unroll
    for (int mt = 0; mt < 4; mt++) {
        int r0 = row0 + wm * 64 + mt * 16 + gr;
#pragma unroll
        for (int nt = 0; nt < 4; nt++) {
            int col = col0 + wn * 32 + nt * 8 + gc;
            float v0x = acc[mt][nt][0] * scale, v0y = acc[mt][nt][1] * scale;
            float v1x = acc[mt][nt][2] * scale, v1y = acc[mt][nt][3] * scale;
            if (BIAS == 1) {
                float bx = bias[col], by = bias[col + 1];
                v0x += bx; v0y += by; v1x += bx; v1y += by;
            } else if (BIAS == 2) {
                float b0v = bias[r0], b1v = bias[r0 + 8];
                v0x += b0v; v0y += b0v; v1x += b1v; v1y += b1v;
            }
            if (RES) {
                float2 ra = *(const float2*)&R[(size_t)r0 * ldr + col];
                float2 rb = *(const float2*)&R[(size_t)(r0 + 8) * ldr + col];
                v0x += ra.x; v0y += ra.y; v1x += rb.x; v1y += rb.y;
            }
            if (ROUND) {
                v0x = rna_tf32(v0x); v0y = rna_tf32(v0y);
                v1x = rna_tf32(v1x); v1y = rna_tf32(v1y);
            }
            *(float2*)&Cm[(size_t)r0 * ldc + col] = make_float2(v0x, v0y);
            *(float2*)&Cm[(size_t)(r0 + 8) * ldc + col] = make_float2(v1x, v1y);
        }
    }
}

template <int BIAS, bool RES, bool ROUND>
static void launch_tn(const float* A, ll sA, int lda,
                      const float* Bg, ll sB, int ldb,
                      float* Cm, ll sC, int ldc,
                      int Md, int Nd, int Kd,
                      const float* bias,
                      const float* R, ll sR, int ldr,
                      float scale, int batch) {
    cudaFuncSetAttribute(gemm_tn<BIAS, RES, ROUND>,
                         cudaFuncAttributeMaxDynamicSharedMemorySize, GSMEM_BYTES);
    dim3 grid(Nd / TNn, Md / TMm, batch);
    gemm_tn<BIAS, RES, ROUND><<<grid, 256, GSMEM_BYTES>>>(
        A, sA, lda, Bg, sB, ldb, Cm, sC, ldc, Kd, bias, R, sR, ldr, scale);
}

// ---------------- driver ----------------

extern "C" void kernel_launch(void* const* d_in, const int* in_sizes, int n_in,
                              void* d_out, int out_size) {
    const float* x = (const float*)d_in[0];
    int pb = (n_in > 1 && in_sizes[1] == 1) ? 2 : 1;
    const float* P[20];
    for (int i = 0; i < 20; i++) P[i] = (const float*)d_in[pb + i];
    float* out = (float*)d_out;

    float *xT, *ctx, *Q, *K, *Vt, *S, *Y, *Z, *Wr;
    cudaGetSymbolAddress((void**)&xT, g_xT);
    cudaGetSymbolAddress((void**)&ctx, g_ctx);
    cudaGetSymbolAddress((void**)&Q, g_Q);
    cudaGetSymbolAddress((void**)&K, g_K);
    cudaGetSymbolAddress((void**)&Vt, g_Vt);
    cudaGetSymbolAddress((void**)&S, g_S);
    cudaGetSymbolAddress((void**)&Y, g_Y);
    cudaGetSymbolAddress((void**)&Z, g_Z);
    cudaGetSymbolAddress((void**)&Wr, g_Wr);

    const int CC = C_ * C_;

    // 1) transpose + selection
    transpose_kernel<<<dim3(N_ / 32, C_ / 32, B_), dim3(32, 8)>>>(x);
    mean_kernel<<<dim3(C_, B_), 256>>>(x);
    score_kernel2<<<dim3(N_ / 8, B_), 256>>>();
    sort_kernel<<<B_, 1024>>>();
    gather_kernel2<<<dim3(M_ / 4, B_, 2), 256>>>();

    // 2) round weights to tf32
    for (int s = 0; s < 2; s++)
        for (int w = 0; w < 4; w++)
            round_copy<<<CC / 256, 256>>>(P[8 * s + 2 * w], Wr + (s * 4 + w) * CC, CC);
    round_copy<<<(2 * CC) / 256, 256>>>(P[16], Wr + 8 * CC, 2 * CC);

    // 3) attention per side
    for (int s = 0; s < 2; s++) {
        const float* Wq = Wr + (s * 4 + 0) * CC; const float* bq = P[8 * s + 1];
        const float* Wk = Wr + (s * 4 + 1) * CC; const float* bk = P[8 * s + 3];
        const float* Wv = Wr + (s * 4 + 2) * CC; const float* bv = P[8 * s + 5];
        const float* Wo = Wr + (s * 4 + 3) * CC; const float* bo = P[8 * s + 7];
        const float* ctxp = ctx + (ll)s * B_ * M_ * C_;

        // Q[b,n,d] = xT[n,:]·Wq[d,:] + bq[d]
        launch_tn<1, false, true>(xT, (ll)N_ * C_, C_, Wq, 0, C_,
                                  Q, (ll)N_ * C_, C_, N_, C_, C_,
                                  bq, nullptr, 0, 0, 1.f, B_);
        // K[b,m,d] = ctx[m,:]·Wk[d,:] + bk[d]
        launch_tn<1, false, true>(ctxp, (ll)M_ * C_, C_, Wk, 0, C_,
                                  K, (ll)M_ * C_, C_, M_, C_, C_,
                                  bk, nullptr, 0, 0, 1.f, B_);
        // Vt[b,d,m] = Wv[d,:]·ctx[m,:] + bv[d]
        launch_tn<2, false, true>(Wv, 0, C_, ctxp, (ll)M_ * C_, C_,
                                  Vt, (ll)C_ * M_, M_, C_, M_, C_,
                                  bv, nullptr, 0, 0, 1.f, B_);
        // S[b,n,m] = Q[n,:]·K[m,:] / 16
        launch_tn<0, false, false>(Q, (ll)N_ * C_, C_, K, (ll)M_ * C_, C_,
                                   S, (ll)N_ * M_, M_, N_, M_, C_,
                                   nullptr, nullptr, 0, 0, 1.f / 16.f, B_);
        softmax_kernel<<<dim3(N_, B_), 256>>>();
        // Y[b,n,d] = P[n,:]·Vt[d,:]
        launch_tn<0, false, true>(S, (ll)N_ * M_, M_, Vt, (ll)C_ * M_, M_,
                                  Y, (ll)N_ * C_, C_, N_, C_, M_,
                                  nullptr, nullptr, 0, 0, 1.f, B_);
        // Z[b,n,e](concat slot s) = Y[n,:]·Wo[e,:] + bo[e] + xT[n,e]
        launch_tn<1, true, true>(Y, (ll)N_ * C_, C_, Wo, 0, C_,
                                 Z + s * C_, (ll)N_ * 2 * C_, 2 * C_,
                                 N_, C_, C_, bo, xT, (ll)N_ * C_, C_, 1.f, B_);
    }

    // 4) fuse conv: out[b,d,n] = Wf[d,:]·Zcat[n,:] + bf[d]
    launch_tn<2, false, false>(Wr + 8 * CC, 0, 2 * C_, Z, (ll)N_ * 2 * C_, 2 * C_,
                               out, (ll)C_ * N_, N_, C_, N_, 2 * C_,
                               P[17], nullptr, 0, 0, 1.f, B_);

    // 5) batchnorm + ReLU in place
    bn_zero<<<1, 256>>>();
    bn_stats<<<dim3(C_, B_), 256>>>(out);
    bn_finalize<<<1, 256>>>(P[18], P[19]);
    bn_final<<<dim3(N_ / 256, C_, B_), 256>>>(out);
}

// round 4
// speedup vs baseline: 4.5792x; 1.4035x over previous
#include <cuda_runtime.h>
#include <cuda_fp16.h>
#include <cstdint>

#define B_ 16
#define C_ 256
#define N_ 4096
#define M_ 1024
#define EPS_ 1e-5f
typedef long long ll;

// ---------------- scratch ----------------
__device__ float g_xT[(ll)B_ * N_ * C_];
__device__ float g_xm[B_ * C_];
__device__ float g_score[B_ * N_];
__device__ int   g_idx[2 * B_ * M_];
__device__ double g_sum[C_];
__device__ double g_sumsq[C_];
__device__ float g_bnw[C_];
__device__ float g_bnb[C_];

__device__ __half g_xTh[(ll)B_ * N_ * C_];
__device__ __half g_ctxh[2LL * B_ * M_ * C_];
__device__ __half g_Qh[(ll)B_ * N_ * C_];
__device__ __half g_Kh[(ll)B_ * M_ * C_];
__device__ __half g_Vth[(ll)B_ * C_ * M_];
__device__ __half g_Sh[(ll)B_ * N_ * M_];
__device__ __half g_Yh[(ll)B_ * N_ * C_];
__device__ __half g_Zh[(ll)B_ * N_ * 2 * C_];
__device__ __half g_Wh[10 * C_ * C_];

// ---------------- PTX ----------------
__device__ __forceinline__ void cp16(uint32_t dst, const void* src) {
    asm volatile("cp.async.cg.shared.global [%0], [%1], 16;" :: "r"(dst), "l"(src));
}
__device__ __forceinline__ void cp_commit() { asm volatile("cp.async.commit_group;"); }
template <int Nw> __device__ __forceinline__ void cp_wait() {
    asm volatile("cp.async.wait_group %0;" :: "n"(Nw));
}
__device__ __forceinline__ void ldsm_x4(uint32_t* r, uint32_t a) {
    asm volatile("ldmatrix.sync.aligned.m8n8.x4.shared.b16 {%0,%1,%2,%3}, [%4];"
        : "=r"(r[0]), "=r"(r[1]), "=r"(r[2]), "=r"(r[3]) : "r"(a));
}
__device__ __forceinline__ void ldsm_x2(uint32_t* r, uint32_t a) {
    asm volatile("ldmatrix.sync.aligned.m8n8.x2.shared.b16 {%0,%1}, [%2];"
        : "=r"(r[0]), "=r"(r[1]) : "r"(a));
}
__device__ __forceinline__ void mma_f16(float* c, const uint32_t* a, const uint32_t* b) {
    asm volatile("mma.sync.aligned.m16n8k16.row.col.f32.f16.f16.f32 "
        "{%0,%1,%2,%3}, {%4,%5,%6,%7}, {%8,%9}, {%0,%1,%2,%3};"
        : "+f"(c[0]), "+f"(c[1]), "+f"(c[2]), "+f"(c[3])
        : "r"(a[0]), "r"(a[1]), "r"(a[2]), "r"(a[3]), "r"(b[0]), "r"(b[1]));
}

// ---------------- small kernels ----------------
__global__ void transpose_kernel(const float* __restrict__ x) {
    __shared__ float t[32][33];
    int b = blockIdx.z, n0 = blockIdx.x * 32, c0 = blockIdx.y * 32;
    int tx = threadIdx.x, ty = threadIdx.y;
    const float* xp = x + (ll)b * C_ * N_;
    float* xtp = g_xT + (ll)b * N_ * C_;
    __half* xhp = g_xTh + (ll)b * N_ * C_;
#pragma unroll
    for (int i = 0; i < 32; i += 8)
        t[ty + i][tx] = xp[(ll)(c0 + ty + i) * N_ + n0 + tx];
    __syncthreads();
#pragma unroll
    for (int i = 0; i < 32; i += 8) {
        float v = t[tx][ty + i];
        xtp[(ll)(n0 + ty + i) * C_ + c0 + tx] = v;
        xhp[(ll)(n0 + ty + i) * C_ + c0 + tx] = __float2half_rn(v);
    }
}

__global__ void mean_kernel(const float* __restrict__ x) {
    int c = blockIdx.x, b = blockIdx.y, t = threadIdx.x;
    const float* p = x + ((ll)b * C_ + c) * N_;
    float s = 0.f;
    for (int i = t; i < N_; i += 256) s += p[i];
    __shared__ float sh[256];
    sh[t] = s; __syncthreads();
    for (int w = 128; w > 0; w >>= 1) { if (t < w) sh[t] += sh[t + w]; __syncthreads(); }
    if (t == 0) g_xm[b * C_ + c] = sh[0] * (1.0f / N_);
}

__global__ void score_kernel2() {
    int b = blockIdx.y;
    int w = threadIdx.x >> 5, lane = threadIdx.x & 31;
    int n = blockIdx.x * 8 + w;
    const float4* row = (const float4*)(g_xT + ((ll)b * N_ + n) * C_);
    const float4* mrow = (const float4*)(g_xm + b * C_);
    float s = 0.f;
#pragma unroll
    for (int j = lane; j < 64; j += 32) {
        float4 v = row[j], m = mrow[j];
        float dx = v.x - m.x, dy = v.y - m.y, dz = v.z - m.z, dw = v.w - m.w;
        s += dx * dx + dy * dy + dz * dz + dw * dw;
    }
#pragma unroll
    for (int o = 16; o; o >>= 1) s += __shfl_xor_sync(0xffffffffu, s, o);
    if (lane == 0) g_score[b * N_ + n] = s;
}

__global__ void sort_kernel() {
    __shared__ float sv[N_];
    __shared__ int   si[N_];
    int b = blockIdx.x, t = threadIdx.x;
    for (int i = t; i < N_; i += 1024) { sv[i] = g_score[b * N_ + i]; si[i] = i; }
    __syncthreads();
    for (int k = 2; k <= N_; k <<= 1)
        for (int j = k >> 1; j > 0; j >>= 1) {
            for (int i = t; i < N_; i += 1024) {
                int ixj = i ^ j;
                if (ixj > i) {
                    bool desc = ((i & k) == 0);
                    float a = sv[i], c = sv[ixj];
                    if (desc ? (a < c) : (a > c)) {
                        sv[i] = c; sv[ixj] = a;
                        int ta = si[i]; si[i] = si[ixj]; si[ixj] = ta;
                    }
                }
            }
            __syncthreads();
        }
    for (int m = t; m < M_; m += 1024) {
        g_idx[0 * B_ * M_ + b * M_ + m] = si[m];
        g_idx[1 * B_ * M_ + b * M_ + m] = si[N_ - M_ + m];
    }
}

__global__ void gather_kernel2() {
    int side = blockIdx.z, b = blockIdx.y;
    int m = blockIdx.x * 4 + (threadIdx.x >> 6);
    int c4 = threadIdx.x & 63;
    int j = g_idx[side * B_ * M_ + b * M_ + m];
    float4 v = ((const float4*)(g_xT + ((ll)b * N_ + j) * C_))[c4];
    __half2* dst = (__half2*)(g_ctxh + (((ll)side * B_ + b) * M_ + m) * C_);
    dst[c4 * 2] = __floats2half2_rn(v.x, v.y);
    dst[c4 * 2 + 1] = __floats2half2_rn(v.z, v.w);
}

__global__ void f2h_kernel(const float* __restrict__ s, __half* __restrict__ d, int n) {
    int i = blockIdx.x * 256 + threadIdx.x;
    if (i < n) d[i] = __float2half_rn(s[i]);
}

__global__ void softmax_kernel() {
    int t = threadIdx.x;  // 256, row of 1024 halves
    ll row = ((ll)blockIdx.y * N_ + blockIdx.x) * M_;
    uint2* p = (uint2*)(g_Sh + row);  // 4 halves per thread
    uint2 raw = p[t];
    __half2 h0 = *(__half2*)&raw.x, h1 = *(__half2*)&raw.y;
    float2 a = __half22float2(h0), bb = __half22float2(h1);
    __shared__ float sh[256];
    float mx = fmaxf(fmaxf(a.x, a.y), fmaxf(bb.x, bb.y));
    sh[t] = mx; __syncthreads();
    for (int w = 128; w > 0; w >>= 1) { if (t < w) sh[t] = fmaxf(sh[t], sh[t + w]); __syncthreads(); }
    float m = sh[0]; __syncthreads();
    a.x = expf(a.x - m); a.y = expf(a.y - m);
    bb.x = expf(bb.x - m); bb.y = expf(bb.y - m);
    sh[t] = a.x + a.y + bb.x + bb.y; __syncthreads();
    for (int w = 128; w > 0; w >>= 1) { if (t < w) sh[t] += sh[t + w]; __syncthreads(); }
    float inv = 1.0f / sh[0];
    h0 = __floats2half2_rn(a.x * inv, a.y * inv);
    h1 = __floats2half2_rn(bb.x * inv, bb.y * inv);
    raw.x = *(uint32_t*)&h0; raw.y = *(uint32_t*)&h1;
    p[t] = raw;
}

__global__ void bn_zero() {
    int t = threadIdx.x;
    if (t < C_) { g_sum[t] = 0.0; g_sumsq[t] = 0.0; }
}

__global__ void bn_stats(const float* __restrict__ pre) {
    int d = blockIdx.x, b = blockIdx.y, t = threadIdx.x;
    const float* p = pre + ((ll)b * C_ + d) * N_;
    float s = 0.f, s2 = 0.f;
    for (int i = t; i < N_; i += 256) { float v = p[i]; s += v; s2 += v * v; }
    __shared__ float sh[256];
    sh[t] = s; __syncthreads();
    for (int w = 128; w > 0; w >>= 1) { if (t < w) sh[t] += sh[t + w]; __syncthreads(); }
    float ts = sh[0]; __syncthreads();
    sh[t] = s2; __syncthreads();
    for (int w = 128; w > 0; w >>= 1) { if (t < w) sh[t] += sh[t + w]; __syncthreads(); }
    float ts2 = sh[0];
    if (t == 0) { atomicAdd(&g_sum[d], (double)ts); atomicAdd(&g_sumsq[d], (double)ts2); }
}

__global__ void bn_finalize(const float* __restrict__ gamma, const float* __restrict__ beta) {
    int d = threadIdx.x;
    double cnt = (double)B_ * N_;
    double mu = g_sum[d] / cnt;
    double var = g_sumsq[d] / cnt - mu * mu;
    float w = gamma[d] * rsqrtf((float)var + EPS_);
    g_bnw[d] = w;
    g_bnb[d] = beta[d] - (float)mu * w;
}

__global__ void bn_final(float* __restrict__ out) {
    int n = blockIdx.x * 256 + threadIdx.x;
    int d = blockIdx.y, b = blockIdx.z;
    ll o = ((ll)b * C_ + d) * N_ + n;
    float v = out[o] * g_bnw[d] + g_bnb[d];
    out[o] = v > 0.f ? v : 0.f;
}

// ---------------- fp16 TN GEMM (128x128, k-chunk 64 halves) ----------------
// C[i,j] = scale*sum_k A[i*lda+k]*B[j*ldb+k] (+bias)(+R[i*ldr+j])
// BIAS: 0 none, 1 per-col, 2 per-row. Strides in elements (halves for A/B).
template <int BIAS, bool RES, typename OutT>
__global__ __launch_bounds__(256, 2)
void gemm_tn(const __half* __restrict__ A, ll sA, int lda,
             const __half* __restrict__ Bg, ll sB, int ldb,
             OutT* __restrict__ Cm, ll sC, int ldc, int Kd,
             const float* __restrict__ bias,
             const float* __restrict__ R, ll sR, int ldr, float scale) {
    extern __shared__ char smc[];
    const uint32_t smu = (uint32_t)__cvta_generic_to_shared(smc);
    const int bz = blockIdx.z;
    A += (ll)bz * sA; Bg += (ll)bz * sB; Cm += (ll)bz * sC;
    if (RES) R += (ll)bz * sR;
    const int row0 = blockIdx.y * 128, col0 = blockIdx.x * 128;
    const int tid = threadIdx.x, lane = tid & 31, warp = tid >> 5;
    const int wm = warp >> 2, wn = warp & 3;
    const int rA = lane & 15, selA = lane >> 4;
    const int tb = lane & 15, rB = tb & 7, midB = tb >> 3;

    float acc[4][4][4];
#pragma unroll
    for (int i = 0; i < 4; i++)
#pragma unroll
        for (int j = 0; j < 4; j++)
#pragma unroll
            for (int q = 0; q < 4; q++) acc[i][j][q] = 0.f;

    const int nT = Kd / 64;
#pragma unroll
    for (int r = 0; r < 4; r++) {  // stage 0
        int lin = tid + r * 256;
        int row = lin >> 3, f4 = lin & 7;
        uint32_t so = (uint32_t)((row * 8 + (f4 ^ (row & 7))) * 16);
        cp16(smu + so, A + (ll)(row0 + row) * lda + f4 * 8);
        cp16(smu + 16384 + so, Bg + (ll)(col0 + row) * ldb + f4 * 8);
    }
    cp_commit();

    for (int t = 0; t < nT; t++) {
        if (t + 1 < nT) {
            int st = (t + 1) & 1, k0 = (t + 1) * 64;
#pragma unroll
            for (int r = 0; r < 4; r++) {
                int lin = tid + r * 256;
                int row = lin >> 3, f4 = lin & 7;
                uint32_t so = (uint32_t)(st * 32768 + (row * 8 + (f4 ^ (row & 7))) * 16);
                cp16(smu + so, A + (ll)(row0 + row) * lda + k0 + f4 * 8);
                cp16(smu + 16384 + so, Bg + (ll)(col0 + row) * ldb + k0 + f4 * 8);
            }
            cp_commit(); cp_wait<1>();
        } else cp_wait<0>();
        __syncthreads();

        uint32_t Au = smu + (uint32_t)((t & 1) * 32768);
        uint32_t Bu = Au + 16384;
#pragma unroll
        for (int kt = 0; kt < 4; kt++) {
            uint32_t af[4][4], bf[4][2];
#pragma unroll
            for (int mt = 0; mt < 4; mt++) {
                int row = wm * 64 + mt * 16 + rA;
                int u = kt * 2 + selA;
                ldsm_x4(af[mt], Au + (uint32_t)((row * 8 + (u ^ (row & 7))) * 16));
            }
#pragma unroll
            for (int nt = 0; nt < 4; nt++) {
                int row = wn * 32 + nt * 8 + rB;
                int u = kt * 2 + midB;
                ldsm_x2(bf[nt], Bu + (uint32_t)((row * 8 + (u ^ (row & 7))) * 16));
            }
#pragma unroll
            for (int mt = 0; mt < 4; mt++)
#pragma unroll
                for (int nt = 0; nt < 4; nt++)
                    mma_f16(acc[mt][nt], af[mt], bf[nt]);
        }
        __syncthreads();
    }

    const int gr = lane >> 2, gc = (lane & 3) * 2;
#pragma unroll
    for (int mt = 0; mt < 4; mt++) {
        int r0 = row0 + wm * 64 + mt * 16 + gr;
#pragma unroll
        for (int nt = 0; nt < 4; nt++) {
            int col = col0 + wn * 32 + nt * 8 + gc;
            float v0x = acc[mt][nt][0] * scale, v0y = acc[mt][nt][1] * scale;
            float v1x = acc[mt][nt][2] * scale, v1y = acc[mt][nt][3] * scale;
            if (BIAS == 1) {
                float bx = bias[col], by = bias[col + 1];
                v0x += bx; v0y += by; v1x += bx; v1y += by;
            } else if (BIAS == 2) {
                float b0v = bias[r0], b1v = bias[r0 + 8];
                v0x += b0v; v0y += b0v; v1x += b1v; v1y += b1v;
            }
            if (RES) {
                float2 ra = *(const float2*)&R[(ll)r0 * ldr + col];
                float2 rb = *(const float2*)&R[(ll)(r0 + 8) * ldr + col];
                v0x += ra.x; v0y += ra.y; v1x += rb.x; v1y += rb.y;
            }
            if constexpr (sizeof(OutT) == 2) {
                *(__half2*)((__half*)Cm + (ll)r0 * ldc + col) = __floats2half2_rn(v0x, v0y);
                *(__half2*)((__half*)Cm + (ll)(r0 + 8) * ldc + col) = __floats2half2_rn(v1x, v1y);
            } else {
                *(float2*)((float*)Cm + (ll)r0 * ldc + col) = make_float2(v0x, v0y);
                *(float2*)((float*)Cm + (ll)(r0 + 8) * ldc + col) = make_float2(v1x, v1y);
            }
        }
    }
}

template <int BIAS, bool RES, typename OutT>
static void launch_tn(const __half* A, ll sA, int lda,
                      const __half* Bg, ll sB, int ldb,
                      OutT* Cm, ll sC, int ldc,
                      int Md, int Nd, int Kd,
                      const float* bias,
                      const float* R, ll sR, int ldr,
                      float scale, int batch) {
    cudaFuncSetAttribute(gemm_tn<BIAS, RES, OutT>,
                         cudaFuncAttributeMaxDynamicSharedMemorySize, 65536);
    dim3 grid(Nd / 128, Md / 128, batch);
    gemm_tn<BIAS, RES, OutT><<<grid, 256, 65536>>>(
        A, sA, lda, Bg, sB, ldb, Cm, sC, ldc, Kd, bias, R, sR, ldr, scale);
}

// ---------------- driver ----------------
extern "C" void kernel_launch(void* const* d_in, const int* in_sizes, int n_in,
                              void* d_out, int out_size) {
    const float* x = (const float*)d_in[0];
    int pb = (n_in > 1 && in_sizes[1] == 1) ? 2 : 1;
    const float* P[20];
    for (int i = 0; i < 20; i++) P[i] = (const float*)d_in[pb + i];
    float* out = (float*)d_out;

    float *xT;
    __half *xTh, *ctxh, *Qh, *Kh, *Vth, *Sh, *Yh, *Zh, *Wh;
    cudaGetSymbolAddress((void**)&xT, g_xT);
    cudaGetSymbolAddress((void**)&xTh, g_xTh);
    cudaGetSymbolAddress((void**)&ctxh, g_ctxh);
    cudaGetSymbolAddress((void**)&Qh, g_Qh);
    cudaGetSymbolAddress((void**)&Kh, g_Kh);
    cudaGetSymbolAddress((void**)&Vth, g_Vth);
    cudaGetSymbolAddress((void**)&Sh, g_Sh);
    cudaGetSymbolAddress((void**)&Yh, g_Yh);
    cudaGetSymbolAddress((void**)&Zh, g_Zh);
    cudaGetSymbolAddress((void**)&Wh, g_Wh);

    const int CC = C_ * C_;

    transpose_kernel<<<dim3(N_ / 32, C_ / 32, B_), dim3(32, 8)>>>(x);
    mean_kernel<<<dim3(C_, B_), 256>>>(x);
    score_kernel2<<<dim3(N_ / 8, B_), 256>>>();
    sort_kernel<<<B_, 1024>>>();
    gather_kernel2<<<dim3(M_ / 4, B_, 2), 256>>>();

    for (int s = 0; s < 2; s++)
        for (int w = 0; w < 4; w++)
            f2h_kernel<<<CC / 256, 256>>>(P[8 * s + 2 * w], Wh + (s * 4 + w) * CC, CC);
    f2h_kernel<<<(2 * CC) / 256, 256>>>(P[16], Wh + 8 * CC, 2 * CC);

    for (int s = 0; s < 2; s++) {
        const __half* Wq = Wh + (s * 4 + 0) * CC; const float* bq = P[8 * s + 1];
        const __half* Wk = Wh + (s * 4 + 1) * CC; const float* bk = P[8 * s + 3];
        const __half* Wv = Wh + (s * 4 + 2) * CC; const float* bv = P[8 * s + 5];
        const __half* Wo = Wh + (s * 4 + 3) * CC; const float* bo = P[8 * s + 7];
        const __half* ctxp = ctxh + (ll)s * B_ * M_ * C_;

        launch_tn<1, false>(xTh, (ll)N_ * C_, C_, Wq, 0, C_,
                            Qh, (ll)N_ * C_, C_, N_, C_, C_, bq, nullptr, 0, 0, 1.f, B_);
        launch_tn<1, false>(ctxp, (ll)M_ * C_, C_, Wk, 0, C_,
                            Kh, (ll)M_ * C_, C_, M_, C_, C_, bk, nullptr, 0, 0, 1.f, B_);
        launch_tn<2, false>(Wv, 0, C_, ctxp, (ll)M_ * C_, C_,
                            Vth, (ll)C_ * M_, M_, C_, M_, C_, bv, nullptr, 0, 0, 1.f, B_);
        launch_tn<0, false>(Qh, (ll)N_ * C_, C_, Kh, (ll)M_ * C_, C_,
                            Sh, (ll)N_ * M_, M_, N_, M_, C_, nullptr, nullptr, 0, 0, 1.f / 16.f, B_);
        softmax_kernel<<<dim3(N_, B_), 256>>>();
        launch_tn<0, false>(Sh, (ll)N_ * M_, M_, Vth, (ll)C_ * M_, M_,
                            Yh, (ll)N_ * C_, C_, N_, C_, M_, nullptr, nullptr, 0, 0, 1.f, B_);
        launch_tn<1, true>(Yh, (ll)N_ * C_, C_, Wo, 0, C_,
                           Zh + s * C_, (ll)N_ * 2 * C_, 2 * C_,
                           N_, C_, C_, bo, xT, (ll)N_ * C_, C_, 1.f, B_);
    }

    launch_tn<2, false>(Wh + 8 * CC, 0, 2 * C_, Zh, (ll)N_ * 2 * C_, 2 * C_,
                        out, (ll)C_ * N_, N_, C_, N_, 2 * C_,
                        P[17], nullptr, 0, 0, 1.f, B_);

    bn_zero<<<1, 256>>>();
    bn_stats<<<dim3(C_, B_), 256>>>(out);
    bn_finalize<<<1, 256>>>(P[18], P[19]);
    bn_final<<<dim3(N_ / 256, C_, B_), 256>>>(out);
}